// round 16
// baseline (speedup 1.0000x reference)
#include <cuda_runtime.h>

// Local 5x5 variance, reflect padding. float32 [16,3,1024,1024] -> same.
//
// R14 structure (3072 CTAs, 2x128-row stages, double-buffered cp.async,
// 256 thr, 3 CTAs/SM, packed f32x2 math) with a trimmed rowsum op tree:
// fma-folded squares (mul+fma instead of mul,mul,add) and a shared middle
// subtree (P2+P3)+P4 feeding both column-pair outputs. ~12% fewer FP ops,
// identical data flow and register footprint.

#define IMG 1024
#define NPLANES 48
#define TW 64
#define STAGE_H 128
#define STAGES 2            // 2 * 128 = 256 rows per CTA
#define SROWS 132           // STAGE_H + 4 halo
#define SC4 18              // 18 float4 = 72 floats per smem row
#define SBUF_ELEMS (SROWS * SC4)          // 2376 float4 per buffer
#define SMEM_BYTES (2 * SBUF_ELEMS * 16)  // 76032 bytes
#define THREADS 256

typedef unsigned long long u64;

__device__ __forceinline__ u64 pk2(float lo, float hi) {
    u64 r; asm("mov.b64 %0, {%1, %2};" : "=l"(r) : "f"(lo), "f"(hi)); return r;
}
__device__ __forceinline__ u64 addx2(u64 a, u64 b) {
    u64 r; asm("add.rn.f32x2 %0, %1, %2;" : "=l"(r) : "l"(a), "l"(b)); return r;
}
__device__ __forceinline__ u64 mulx2(u64 a, u64 b) {
    u64 r; asm("mul.rn.f32x2 %0, %1, %2;" : "=l"(r) : "l"(a), "l"(b)); return r;
}
__device__ __forceinline__ u64 fmax2(u64 a, u64 b, u64 c) {
    u64 r; asm("fma.rn.f32x2 %0, %1, %2, %3;" : "=l"(r) : "l"(a), "l"(b), "l"(c)); return r;
}
__device__ __forceinline__ void upk2(u64 v, float& lo, float& hi) {
    asm("mov.b64 {%0, %1}, %2;" : "=f"(lo), "=f"(hi) : "l"(v));
}

__device__ __forceinline__ int reflect_idx(int i, int n) {
    if (i < 0) i = -i;
    if (i >= n) i = 2 * (n - 1) - i;
    return i;
}

__device__ __forceinline__ void cp_async16(void* smem_dst, const void* gsrc) {
    unsigned sa = (unsigned)__cvta_generic_to_shared(smem_dst);
    asm volatile("cp.async.cg.shared.global [%0], [%1], 16;\n" :: "r"(sa), "l"(gsrc));
}

// Packed horizontal 5-sums of x and x^2 for 4 output columns.
// Window floats 2..9 of (a|b|c); column pairs (0,1) and (2,3).
// Trimmed tree: shared middle subtree + fma-folded squares.
__device__ __forceinline__ void rowsum_pk(float4 a, float4 b, float4 c,
                                          u64& s01, u64& s23,
                                          u64& t01, u64& t23) {
    const float x0 = a.z, x1 = a.w, x2 = b.x, x3 = b.y;
    const float x4 = b.z, x5 = b.w, x6 = c.x, x7 = c.y;

    const u64 P0 = pk2(x0, x1), P1 = pk2(x1, x2), P2 = pk2(x2, x3);
    const u64 P3 = pk2(x3, x4), P4 = pk2(x4, x5), P5 = pk2(x5, x6);
    const u64 P6 = pk2(x6, x7);

    // x sums: 6 adds (shared m)
    const u64 e01 = addx2(P0, P1);
    const u64 e23 = addx2(P2, P3);
    const u64 e56 = addx2(P5, P6);
    const u64 m   = addx2(e23, P4);
    s01 = addx2(e01, m);
    s23 = addx2(m, e56);

    // x^2 sums: 3 muls + 4 fmas + 2 adds (shared mt)
    const u64 q01 = fmax2(P1, P1, mulx2(P0, P0));
    const u64 q23 = fmax2(P3, P3, mulx2(P2, P2));
    const u64 mt  = fmax2(P4, P4, q23);
    const u64 q56 = fmax2(P6, P6, mulx2(P5, P5));
    t01 = addx2(q01, mt);
    t23 = addx2(mt, q56);
}

__global__ __launch_bounds__(THREADS, 3)
void locvar5_kernel(const float* __restrict__ in, float* __restrict__ out) {
    extern __shared__ float4 sbuf[];   // 2 buffers of SBUF_ELEMS

    const int plane = blockIdx.z;
    const float* __restrict__ src = in + (size_t)plane * IMG * IMG;
    float* __restrict__ dst = out + (size_t)plane * IMG * IMG;

    const int bx = blockIdx.x * TW;
    const int byBase = blockIdx.y * (STAGES * STAGE_H);
    const int tid = threadIdx.x;
    const bool colEdge = (bx == 0) || (bx + TW == IMG);

    const int tx4 = tid & 15;
    const int ty  = tid >> 4;          // 16 strips of 8 rows

    const int rowInit = tid / SC4;     // one div/mod total, reused per stage
    const int c4Init  = tid - rowInit * SC4;

    // ---- stage loader: async copies with incremental indexing ----
    auto load_stage = [&](int s, int buf) {
        float4* sb = sbuf + buf * SBUF_ELEMS;
        const int r0 = byBase + s * STAGE_H - 2;
        const bool rowsInterior = (r0 >= 0) && (r0 + SROWS <= IMG);
        int row = rowInit;
        int c4  = c4Init;
        while (row < SROWS) {
            const int gy = rowsInterior ? (r0 + row) : reflect_idx(r0 + row, IMG);
            const int gx = bx - 4 + c4 * 4;
            float4* sdst = sb + row * SC4 + c4;
            if (!colEdge || (c4 >= 1 && c4 <= 16)) {
                cp_async16(sdst, src + (size_t)gy * IMG + gx);
            } else {
                float4 v;
                v.x = src[(size_t)gy * IMG + reflect_idx(gx + 0, IMG)];
                v.y = src[(size_t)gy * IMG + reflect_idx(gx + 1, IMG)];
                v.z = src[(size_t)gy * IMG + reflect_idx(gx + 2, IMG)];
                v.w = src[(size_t)gy * IMG + reflect_idx(gx + 3, IMG)];
                *sdst = v;
            }
            // advance by 256 items: 256 = 14*18 + 4
            c4 += 4; row += 14;
            if (c4 >= SC4) { c4 -= SC4; ++row; }
        }
        asm volatile("cp.async.commit_group;\n" ::: "memory");
    };

    // ---- prologue: load stage 0, wait ----
    load_stage(0, 0);
    asm volatile("cp.async.wait_group 0;\n" ::: "memory");
    __syncthreads();

    const float inv_n = 1.0f / 25.0f;
    const u64 INV  = pk2(inv_n, inv_n);
    const u64 NINV = pk2(-inv_n, -inv_n);

    #pragma unroll
    for (int s = 0; s < STAGES; ++s) {
        if (s + 1 < STAGES) load_stage(s + 1, (s + 1) & 1);

        // ---- compute stage s: 8 output rows per thread ----
        const float4* sp = sbuf + (s & 1) * SBUF_ELEMS + (ty * 8) * SC4 + tx4;

        u64 hs01[5], hs23[5], ht01[5], ht23[5];
        #pragma unroll
        for (int j = 0; j < 4; ++j)
            rowsum_pk(sp[j * SC4], sp[j * SC4 + 1], sp[j * SC4 + 2],
                      hs01[j], hs23[j], ht01[j], ht23[j]);

        float4* op = (float4*)(dst + (size_t)(byBase + s * STAGE_H + ty * 8) * IMG
                                   + bx + tx4 * 4);
        #pragma unroll
        for (int j = 4; j < 12; ++j) {
            const int w = j % 5;
            rowsum_pk(sp[j * SC4], sp[j * SC4 + 1], sp[j * SC4 + 2],
                      hs01[w], hs23[w], ht01[w], ht23[w]);

            const u64 S01 = addx2(addx2(hs01[0], hs01[1]),
                                  addx2(hs01[2], addx2(hs01[3], hs01[4])));
            const u64 S23 = addx2(addx2(hs23[0], hs23[1]),
                                  addx2(hs23[2], addx2(hs23[3], hs23[4])));
            const u64 T01 = addx2(addx2(ht01[0], ht01[1]),
                                  addx2(ht01[2], addx2(ht01[3], ht01[4])));
            const u64 T23 = addx2(addx2(ht23[0], ht23[1]),
                                  addx2(ht23[2], addx2(ht23[3], ht23[4])));

            // var = T/25 - (S/25)^2  ==  (S*inv)*(S*-inv) + T*inv
            const u64 v01 = fmax2(mulx2(S01, INV), mulx2(S01, NINV), mulx2(T01, INV));
            const u64 v23 = fmax2(mulx2(S23, INV), mulx2(S23, NINV), mulx2(T23, INV));

            float4 o;
            upk2(v01, o.x, o.y);
            upk2(v23, o.z, o.w);
            *op = o;
            op += IMG / 4;
        }

        if (s + 1 < STAGES) {
            asm volatile("cp.async.wait_group 0;\n" ::: "memory");
            __syncthreads();
        }
    }
}

extern "C" void kernel_launch(void* const* d_in, const int* in_sizes, int n_in,
                              void* d_out, int out_size) {
    const float* in = (const float*)d_in[0];
    float* out = (float*)d_out;
    cudaFuncSetAttribute(locvar5_kernel,
                         cudaFuncAttributeMaxDynamicSharedMemorySize, SMEM_BYTES);
    dim3 grid(IMG / TW, IMG / (STAGES * STAGE_H), NPLANES);
    locvar5_kernel<<<grid, THREADS, SMEM_BYTES>>>(in, out);
}

// round 17
// speedup vs baseline: 1.2066x; 1.2066x over previous
#include <cuda_runtime.h>
#include <cstdint>

// Local 5x5 variance, reflect padding. float32 [16,3,1024,1024] -> same.
//
// R14 compute core (3072 CTAs, 2x128-row stages, 256 thr, 3 CTAs/SM,
// packed f32x2 math) with the loader rebuilt on cp.async.bulk (UBLKCP):
// one 288B bulk copy per tile row (132 per stage) completing on an
// mbarrier, instead of 2376 per-16B cp.asyncs. Both stages' loads are
// issued up front; each stage waits only its own mbarrier. Row reflection
// is free (per-row gy); column reflection = post-wait smem patch on the
// two edge CTA columns.

#define IMG 1024
#define NPLANES 48
#define TW 64
#define STAGE_H 128
#define STAGES 2
#define SROWS 132           // STAGE_H + 4 halo
#define SC4 18              // 18 float4 = 72 floats per smem row
#define SBUF_ELEMS (SROWS * SC4)
#define SMEM_BYTES (2 * SBUF_ELEMS * 16)   // 76032 B dynamic
#define THREADS 256

typedef unsigned long long u64;

__device__ __forceinline__ u64 pk2(float lo, float hi) {
    u64 r; asm("mov.b64 %0, {%1, %2};" : "=l"(r) : "f"(lo), "f"(hi)); return r;
}
__device__ __forceinline__ u64 addx2(u64 a, u64 b) {
    u64 r; asm("add.rn.f32x2 %0, %1, %2;" : "=l"(r) : "l"(a), "l"(b)); return r;
}
__device__ __forceinline__ u64 mulx2(u64 a, u64 b) {
    u64 r; asm("mul.rn.f32x2 %0, %1, %2;" : "=l"(r) : "l"(a), "l"(b)); return r;
}
__device__ __forceinline__ u64 fmax2(u64 a, u64 b, u64 c) {
    u64 r; asm("fma.rn.f32x2 %0, %1, %2, %3;" : "=l"(r) : "l"(a), "l"(b), "l"(c)); return r;
}
__device__ __forceinline__ void upk2(u64 v, float& lo, float& hi) {
    asm("mov.b64 {%0, %1}, %2;" : "=f"(lo), "=f"(hi) : "l"(v));
}

__device__ __forceinline__ int reflect_idx(int i, int n) {
    if (i < 0) i = -i;
    if (i >= n) i = 2 * (n - 1) - i;
    return i;
}

__device__ __forceinline__ unsigned s2u(const void* p) {
    return (unsigned)__cvta_generic_to_shared(p);
}
__device__ __forceinline__ void mbar_init(void* m, unsigned cnt) {
    asm volatile("mbarrier.init.shared.b64 [%0], %1;" :: "r"(s2u(m)), "r"(cnt) : "memory");
}
__device__ __forceinline__ void mbar_expect(void* m, unsigned bytes) {
    asm volatile("mbarrier.arrive.expect_tx.shared.b64 _, [%0], %1;"
                 :: "r"(s2u(m)), "r"(bytes) : "memory");
}
__device__ __forceinline__ void mbar_wait(void* m, unsigned parity) {
    asm volatile(
        "{\n\t.reg .pred P;\n\t"
        "WAIT_%=:\n\t"
        "mbarrier.try_wait.parity.acquire.cta.shared::cta.b64 P, [%0], %1, 0x989680;\n\t"
        "@!P bra WAIT_%=;\n\t}"
        :: "r"(s2u(m)), "r"(parity) : "memory");
}
__device__ __forceinline__ void bulk_g2s(void* sdst, const void* gsrc,
                                         unsigned bytes, void* m) {
    asm volatile(
        "cp.async.bulk.shared::cluster.global.mbarrier::complete_tx::bytes "
        "[%0], [%1], %2, [%3];"
        :: "r"(s2u(sdst)), "l"(gsrc), "r"(bytes), "r"(s2u(m)) : "memory");
}

// Packed horizontal 5-sums of x and x^2 for 4 output columns (R14 tree).
__device__ __forceinline__ void rowsum_pk(float4 a, float4 b, float4 c,
                                          u64& s01, u64& s23,
                                          u64& t01, u64& t23) {
    const float x0 = a.z, x1 = a.w, x2 = b.x, x3 = b.y;
    const float x4 = b.z, x5 = b.w, x6 = c.x, x7 = c.y;

    const u64 P0 = pk2(x0, x1), P1 = pk2(x1, x2), P2 = pk2(x2, x3);
    const u64 P3 = pk2(x3, x4), P4 = pk2(x4, x5), P5 = pk2(x5, x6);
    const u64 P6 = pk2(x6, x7);

    const u64 p01 = addx2(P0, P1);
    const u64 p23 = addx2(P2, P3);
    const u64 p45 = addx2(P4, P5);
    s01 = addx2(p01, addx2(p23, P4));
    s23 = addx2(p23, addx2(p45, P6));

    const u64 Q0 = mulx2(P0, P0), Q1 = mulx2(P1, P1), Q2 = mulx2(P2, P2);
    const u64 Q3 = mulx2(P3, P3), Q4 = mulx2(P4, P4), Q5 = mulx2(P5, P5);
    const u64 Q6 = mulx2(P6, P6);

    const u64 q01 = addx2(Q0, Q1);
    const u64 q23 = addx2(Q2, Q3);
    const u64 q45 = addx2(Q4, Q5);
    t01 = addx2(q01, addx2(q23, Q4));
    t23 = addx2(q23, addx2(q45, Q6));
}

__global__ __launch_bounds__(THREADS, 3)
void locvar5_kernel(const float* __restrict__ in, float* __restrict__ out) {
    extern __shared__ float4 sbuf[];       // 2 buffers of SBUF_ELEMS
    __shared__ u64 mbars[2];

    const int plane = blockIdx.z;
    const float* __restrict__ src = in + (size_t)plane * IMG * IMG;
    float* __restrict__ dst = out + (size_t)plane * IMG * IMG;

    const int bx = blockIdx.x * TW;
    const int byBase = blockIdx.y * (STAGES * STAGE_H);
    const int tid = threadIdx.x;
    const bool colL = (bx == 0);
    const bool colR = (bx + TW == IMG);
    const bool colEdge = colL || colR;

    const unsigned szB = colEdge ? 272u : 288u;   // 17 or 18 x 16B per row
    const unsigned txB = (unsigned)SROWS * szB;

    if (tid == 0) {
        mbar_init(&mbars[0], 1);
        mbar_init(&mbars[1], 1);
        mbar_expect(&mbars[0], txB);
        mbar_expect(&mbars[1], txB);
    }
    __syncthreads();

    // ---- issue all loads for both stages up front: one bulk per row ----
    if (tid < SROWS) {
        const int gx0   = colL ? 0 : (bx - 4);
        const int dOff  = colL ? 1 : 0;           // left edge lands at col 4
        #pragma unroll
        for (int s = 0; s < STAGES; ++s) {
            const int gy = reflect_idx(byBase + s * STAGE_H - 2 + tid, IMG);
            bulk_g2s(sbuf + s * SBUF_ELEMS + tid * SC4 + dOff,
                     src + (size_t)gy * IMG + gx0, szB, &mbars[s]);
        }
    }

    const float inv_n = 1.0f / 25.0f;
    const u64 INV  = pk2(inv_n, inv_n);
    const u64 NINV = pk2(-inv_n, -inv_n);

    const int tx4 = tid & 15;
    const int ty  = tid >> 4;                     // 16 strips of 8 rows

    #pragma unroll
    for (int s = 0; s < STAGES; ++s) {
        mbar_wait(&mbars[s], 0);

        if (colEdge) {
            // patch reflected columns from data already in the tile
            float4* sb = sbuf + s * SBUF_ELEMS;
            for (int i = tid; i < SROWS * 4; i += THREADS) {
                const int row = i >> 2, c = i & 3;
                float* fr = (float*)(sb + row * SC4);
                if (colL) fr[c]      = fr[8 - c];     // cols 0..3  <- 8..5
                else      fr[68 + c] = fr[66 - c];    // cols 68..71 <- 66..63
            }
            __syncthreads();
        }

        // ---- compute stage s: 8 output rows per thread ----
        const float4* sp = sbuf + s * SBUF_ELEMS + (ty * 8) * SC4 + tx4;

        u64 hs01[5], hs23[5], ht01[5], ht23[5];
        #pragma unroll
        for (int j = 0; j < 4; ++j)
            rowsum_pk(sp[j * SC4], sp[j * SC4 + 1], sp[j * SC4 + 2],
                      hs01[j], hs23[j], ht01[j], ht23[j]);

        float4* op = (float4*)(dst + (size_t)(byBase + s * STAGE_H + ty * 8) * IMG
                                   + bx + tx4 * 4);
        #pragma unroll
        for (int j = 4; j < 12; ++j) {
            const int w = j % 5;
            rowsum_pk(sp[j * SC4], sp[j * SC4 + 1], sp[j * SC4 + 2],
                      hs01[w], hs23[w], ht01[w], ht23[w]);

            const u64 S01 = addx2(addx2(hs01[0], hs01[1]),
                                  addx2(hs01[2], addx2(hs01[3], hs01[4])));
            const u64 S23 = addx2(addx2(hs23[0], hs23[1]),
                                  addx2(hs23[2], addx2(hs23[3], hs23[4])));
            const u64 T01 = addx2(addx2(ht01[0], ht01[1]),
                                  addx2(ht01[2], addx2(ht01[3], ht01[4])));
            const u64 T23 = addx2(addx2(ht23[0], ht23[1]),
                                  addx2(ht23[2], addx2(ht23[3], ht23[4])));

            // var = T/25 - (S/25)^2 == (S*inv)*(S*-inv) + T*inv
            const u64 v01 = fmax2(mulx2(S01, INV), mulx2(S01, NINV), mulx2(T01, INV));
            const u64 v23 = fmax2(mulx2(S23, INV), mulx2(S23, NINV), mulx2(T23, INV));

            float4 o;
            upk2(v01, o.x, o.y);
            upk2(v23, o.z, o.w);
            *op = o;
            op += IMG / 4;
        }
    }
}

extern "C" void kernel_launch(void* const* d_in, const int* in_sizes, int n_in,
                              void* d_out, int out_size) {
    const float* in = (const float*)d_in[0];
    float* out = (float*)d_out;
    cudaFuncSetAttribute(locvar5_kernel,
                         cudaFuncAttributeMaxDynamicSharedMemorySize, SMEM_BYTES);
    dim3 grid(IMG / TW, IMG / (STAGES * STAGE_H), NPLANES);
    locvar5_kernel<<<grid, THREADS, SMEM_BYTES>>>(in, out);
}